// round 7
// baseline (speedup 1.0000x reference)
#include <cuda_runtime.h>
#include <cuda_fp16.h>

#define NN 50000
#define NE 800000
#define DIN 96
#define HID 128
#define NG 256
#define NCAT 256   // [W_rel | W_root] concatenated output width

// ---------------- scratch (__device__ globals; allocation-free) ----------------
// NOTE: g_deg starts zero (static init) and k_scan re-zeros it after use, so the
// zero-degree invariant holds on every graph replay with no dedicated kernel.
__device__ __align__(16) int    g_deg[NN];
__device__ __align__(16) int    g_off[NN + 1];
__device__ __align__(16) int    g_cur[NN];
__device__ __align__(16) int2   g_edge[NE];          // (src, w-as-int)
__device__ __align__(16) float  g_Wc1[DIN * NCAT];
__device__ __align__(16) float  g_Wc2[HID * NCAT];
__device__ __align__(16) __half g_Yr16[(size_t)NN * HID];  // rel half, fp16 (gathered)
__device__ __align__(16) float  g_Yroot[(size_t)NN * HID]; // root half, fp32
__device__ __align__(16) float  g_h1[(size_t)NN * HID];
__device__ __align__(16) float  g_h2[(size_t)NN * HID];

// ---------------- CSR build ----------------
__global__ void k_count(const int* __restrict__ ei) {
    int e = blockIdx.x * blockDim.x + threadIdx.x;
    if (e < NE) atomicAdd(&g_deg[ei[NE + e]], 1);
}

__global__ void k_scan() {
    __shared__ int wsum[32];
    const int tid = threadIdx.x;
    const int CH = (NN + 1023) / 1024;
    const int base = tid * CH;
    int s = 0;
    for (int i = 0; i < CH; i++) {
        int idx = base + i;
        if (idx < NN) s += g_deg[idx];
    }
    int lane = tid & 31, w = tid >> 5;
    int v = s;
    #pragma unroll
    for (int o = 1; o < 32; o <<= 1) {
        int n = __shfl_up_sync(0xffffffffu, v, o);
        if (lane >= o) v += n;
    }
    if (lane == 31) wsum[w] = v;
    __syncthreads();
    if (w == 0) {
        int x = wsum[lane];
        #pragma unroll
        for (int o = 1; o < 32; o <<= 1) {
            int n = __shfl_up_sync(0xffffffffu, x, o);
            if (lane >= o) x += n;
        }
        wsum[lane] = x;
    }
    __syncthreads();
    int excl = v - s + (w > 0 ? wsum[w - 1] : 0);
    int run = excl;
    for (int i = 0; i < CH; i++) {
        int idx = base + i;
        if (idx < NN) {
            g_off[idx] = run;
            g_cur[idx] = run;
            run += g_deg[idx];
            g_deg[idx] = 0;   // re-zero for next replay (replaces k_zero_deg)
        }
    }
    if (tid == 1023) g_off[NN] = run;
}

__global__ void k_scatter(const int* __restrict__ ei, const float* __restrict__ ea) {
    int e = blockIdx.x * blockDim.x + threadIdx.x;
    if (e < NE) {
        int d = ei[NE + e];
        int p = atomicAdd(&g_cur[d], 1);
        g_edge[p] = make_int2(ei[e], __float_as_int(ea[e]));
    }
}

// ---------------- weight prep: transpose + concat into [K][256] ----------------
__global__ void k_prep_w(const float* __restrict__ Wr1, const float* __restrict__ Wro1,
                         const float* __restrict__ Wr3, const float* __restrict__ Wro3) {
    int idx = blockIdx.x * blockDim.x + threadIdx.x;
    const int n1 = DIN * NCAT;
    if (idx < n1) {
        int k = idx / NCAT, j = idx % NCAT;
        g_Wc1[idx] = (j < HID) ? Wr1[j * DIN + k] : Wro1[(j - HID) * DIN + k];
    } else if (idx < n1 + HID * NCAT) {
        int t = idx - n1;
        int k = t / NCAT, j = t % NCAT;
        g_Wc2[t] = (j < HID) ? Wr3[j * HID + k] : Wro3[(j - HID) * HID + k];
    }
}

// ---------------- fp32 SGEMM: double-buffered, BK=16, reg-prefetch -------------
template <int K>
__global__ __launch_bounds__(256) void k_sgemm(const float* __restrict__ Ax) {
    const float* __restrict__ A = (K == 96) ? Ax : g_h1;
    const float* __restrict__ B = (K == 96) ? g_Wc1 : g_Wc2;
    __shared__ float As[2][16][128];
    __shared__ float Bs[2][16][128];
    const int tid = threadIdx.x;
    const int m0 = blockIdx.y * 128;
    const int n0 = blockIdx.x * 128;
    const int ty = tid >> 4, tx = tid & 15;
    const int NI = K / 16;

    const int aR0 = tid >> 2, aC0 = (tid & 3) * 4;
    const int bK0 = tid >> 5, bN0 = (tid & 31) * 4;

    float4 pa[2], pb[2];
    auto ldA = [&](int k0) {
        #pragma unroll
        for (int i = 0; i < 2; i++) {
            int r = aR0 + i * 64;
            int gr = m0 + r;
            pa[i] = (gr < NN) ? *(const float4*)(A + (size_t)gr * K + k0 + aC0)
                              : make_float4(0.f, 0.f, 0.f, 0.f);
        }
    };
    auto ldB = [&](int k0) {
        #pragma unroll
        for (int i = 0; i < 2; i++) {
            int kk = bK0 + i * 8;
            pb[i] = *(const float4*)(B + (size_t)(k0 + kk) * NCAT + n0 + bN0);
        }
    };
    auto stAB = [&](int buf) {
        #pragma unroll
        for (int i = 0; i < 2; i++) {
            int r = aR0 + i * 64;
            As[buf][aC0 + 0][r] = pa[i].x;
            As[buf][aC0 + 1][r] = pa[i].y;
            As[buf][aC0 + 2][r] = pa[i].z;
            As[buf][aC0 + 3][r] = pa[i].w;
            *(float4*)&Bs[buf][bK0 + i * 8][bN0] = pb[i];
        }
    };

    float acc[8][8];
    #pragma unroll
    for (int i = 0; i < 8; i++)
        #pragma unroll
        for (int j = 0; j < 8; j++) acc[i][j] = 0.f;

    ldA(0); ldB(0);
    stAB(0);
    __syncthreads();

    int buf = 0;
    for (int it = 0; it < NI; it++) {
        if (it + 1 < NI) { ldA((it + 1) * 16); ldB((it + 1) * 16); }
        #pragma unroll
        for (int k = 0; k < 16; k++) {
            const float4 a0 = *(const float4*)&As[buf][k][ty * 8];
            const float4 a1 = *(const float4*)&As[buf][k][ty * 8 + 4];
            const float4 b0 = *(const float4*)&Bs[buf][k][tx * 8];
            const float4 b1 = *(const float4*)&Bs[buf][k][tx * 8 + 4];
            const float ar[8] = {a0.x, a0.y, a0.z, a0.w, a1.x, a1.y, a1.z, a1.w};
            const float br[8] = {b0.x, b0.y, b0.z, b0.w, b1.x, b1.y, b1.z, b1.w};
            #pragma unroll
            for (int i = 0; i < 8; i++)
                #pragma unroll
                for (int j = 0; j < 8; j++)
                    acc[i][j] = fmaf(ar[i], br[j], acc[i][j]);
        }
        if (it + 1 < NI) stAB(buf ^ 1);
        __syncthreads();
        buf ^= 1;
    }

    const bool relPart = (blockIdx.x == 0);
    #pragma unroll
    for (int i = 0; i < 8; i++) {
        int r = m0 + ty * 8 + i;
        if (r >= NN) continue;
        if (relPart) {
            __half2 h0 = __floats2half2_rn(acc[i][0], acc[i][1]);
            __half2 h1 = __floats2half2_rn(acc[i][2], acc[i][3]);
            __half2 h2 = __floats2half2_rn(acc[i][4], acc[i][5]);
            __half2 h3 = __floats2half2_rn(acc[i][6], acc[i][7]);
            uint4 v;
            v.x = *(unsigned*)&h0; v.y = *(unsigned*)&h1;
            v.z = *(unsigned*)&h2; v.w = *(unsigned*)&h3;
            *(uint4*)(g_Yr16 + (size_t)r * HID + tx * 8) = v;
        } else {
            float* d0 = g_Yroot + (size_t)r * HID + tx * 8;
            *(float4*)(d0)     = make_float4(acc[i][0], acc[i][1], acc[i][2], acc[i][3]);
            *(float4*)(d0 + 4) = make_float4(acc[i][4], acc[i][5], acc[i][6], acc[i][7]);
        }
    }
}

// ---------------- edge aggregation: fp16 gather, warp per node -----------------
__global__ void k_agg(const float* __restrict__ bias, int layer) {
    int node = (blockIdx.x * blockDim.x + threadIdx.x) >> 5;
    if (node >= NN) return;
    int lane = threadIdx.x & 31;
    int beg = g_off[node], end = g_off[node + 1];
    float ax = 0.f, ay = 0.f, az = 0.f, aw = 0.f;
    float bx = 0.f, by = 0.f, bz = 0.f, bw = 0.f;
    int e = beg;
    for (; e + 1 < end; e += 2) {
        int2 e0 = g_edge[e];
        int2 e1 = g_edge[e + 1];
        uint2 v0 = *(const uint2*)(g_Yr16 + (size_t)e0.x * HID + 4 * lane);
        uint2 v1 = *(const uint2*)(g_Yr16 + (size_t)e1.x * HID + 4 * lane);
        float w0 = __int_as_float(e0.y);
        float w1 = __int_as_float(e1.y);
        float2 p00 = __half22float2(*(__half2*)&v0.x);
        float2 p01 = __half22float2(*(__half2*)&v0.y);
        float2 p10 = __half22float2(*(__half2*)&v1.x);
        float2 p11 = __half22float2(*(__half2*)&v1.y);
        ax = fmaf(p00.x, w0, ax); ay = fmaf(p00.y, w0, ay);
        az = fmaf(p01.x, w0, az); aw = fmaf(p01.y, w0, aw);
        bx = fmaf(p10.x, w1, bx); by = fmaf(p10.y, w1, by);
        bz = fmaf(p11.x, w1, bz); bw = fmaf(p11.y, w1, bw);
    }
    if (e < end) {
        int2 e0 = g_edge[e];
        uint2 v0 = *(const uint2*)(g_Yr16 + (size_t)e0.x * HID + 4 * lane);
        float w0 = __int_as_float(e0.y);
        float2 p00 = __half22float2(*(__half2*)&v0.x);
        float2 p01 = __half22float2(*(__half2*)&v0.y);
        ax = fmaf(p00.x, w0, ax); ay = fmaf(p00.y, w0, ay);
        az = fmaf(p01.x, w0, az); aw = fmaf(p01.y, w0, aw);
    }
    ax += bx; ay += by; az += bz; aw += bw;
    float4 r = *(const float4*)(g_Yroot + (size_t)node * HID + 4 * lane);
    float4 b = *(const float4*)(bias + 4 * lane);
    ax += r.x + b.x;
    ay += r.y + b.y;
    az += r.z + b.z;
    aw += r.w + b.w;
    float* H;
    if (layer == 1) {
        ax = fmaxf(ax, 0.f); ay = fmaxf(ay, 0.f);
        az = fmaxf(az, 0.f); aw = fmaxf(aw, 0.f);
        H = g_h1;
    } else {
        H = g_h2;
    }
    *(float4*)(H + (size_t)node * HID + 4 * lane) = make_float4(ax, ay, az, aw);
}

// ---------------- pooling + head (batch sorted -> binary search) ----------------
__global__ void k_pool(const int* __restrict__ batch, const float* __restrict__ Wl,
                       const float* __restrict__ bl, float* __restrict__ out) {
    int g = blockIdx.x;
    int c = threadIdx.x;
    int lo = 0, hi = NN;
    while (lo < hi) {
        int m = (lo + hi) >> 1;
        if (batch[m] < g) lo = m + 1; else hi = m;
    }
    int l = lo, h = NN;
    while (l < h) {
        int m = (l + h) >> 1;
        if (batch[m] < g + 1) l = m + 1; else h = m;
    }
    int cnt = l - lo;
    float s = 0.f;
    for (int i = lo; i < l; i++) s += g_h2[(size_t)i * HID + c];
    float p = s / fmaxf((float)cnt, 1.f);
    float v = p * Wl[c];
    __shared__ float red[128];
    red[c] = v;
    __syncthreads();
    for (int st = 64; st > 0; st >>= 1) {
        if (c < st) red[c] += red[c + st];
        __syncthreads();
    }
    if (c == 0) out[g] = fmaxf(red[0] + bl[0], 0.f);
}

// ---------------- launch (forked capture: CSR chain ∥ prep+GEMM1) --------------
extern "C" void kernel_launch(void* const* d_in, const int* in_sizes, int n_in,
                              void* d_out, int out_size) {
    const float* x     = (const float*)d_in[0];
    const int*   ei    = (const int*)d_in[1];
    const int*   batch = (const int*)d_in[2];
    const float* ea    = (const float*)d_in[3];
    const float* Wr1   = (const float*)d_in[4];
    const float* b1    = (const float*)d_in[5];
    const float* Wro1  = (const float*)d_in[6];
    const float* Wr3   = (const float*)d_in[7];
    const float* b3    = (const float*)d_in[8];
    const float* Wro3  = (const float*)d_in[9];
    const float* Wl    = (const float*)d_in[10];
    const float* bl    = (const float*)d_in[11];
    float* out = (float*)d_out;

    // Persistent side stream + events (handles created once, on the correctness
    // call which runs before capture; capture sees only record/wait/launch nodes).
    static cudaStream_t s2 = nullptr;
    static cudaEvent_t evFork = nullptr, evJoin = nullptr;
    if (!s2) {
        cudaStreamCreateWithFlags(&s2, cudaStreamNonBlocking);
        cudaEventCreateWithFlags(&evFork, cudaEventDisableTiming);
        cudaEventCreateWithFlags(&evJoin, cudaEventDisableTiming);
    }

    // fork: side stream builds CSR while main stream does weights + GEMM1
    cudaEventRecord(evFork, 0);
    cudaStreamWaitEvent(s2, evFork, 0);

    k_count<<<(NE + 255) / 256, 256, 0, s2>>>(ei);
    k_scan<<<1, 1024, 0, s2>>>();
    k_scatter<<<(NE + 255) / 256, 256, 0, s2>>>(ei, ea);
    cudaEventRecord(evJoin, s2);

    k_prep_w<<<((DIN + HID) * NCAT + 255) / 256, 256>>>(Wr1, Wro1, Wr3, Wro3);
    dim3 ggrid(2, (NN + 127) / 128);
    k_sgemm<96><<<ggrid, 256>>>(x);

    // join: aggregation needs both GEMM1 output and the CSR
    cudaStreamWaitEvent(0, evJoin, 0);
    k_agg<<<(NN * 32 + 255) / 256, 256>>>(b1, 1);

    // layer 2
    k_sgemm<128><<<ggrid, 256>>>(nullptr);
    k_agg<<<(NN * 32 + 255) / 256, 256>>>(b3, 2);
    // pool + head
    k_pool<<<NG, 128>>>(batch, Wl, bl, out);
}

// round 8
// speedup vs baseline: 1.3879x; 1.3879x over previous
#include <cuda_runtime.h>
#include <cuda_fp16.h>

#define NN 50000
#define NE 800000
#define DIN 96
#define HID 128
#define NG 256
#define NCAT 256   // [W_rel1 | W_root1] concatenated output width

// ---------------- scratch (__device__ globals; allocation-free) ----------------
// g_deg starts zero (static init) and k_scan re-zeros it after use.
__device__ __align__(16) int    g_deg[NN];
__device__ __align__(16) int    g_off[NN + 1];
__device__ __align__(16) int    g_cur[NN];
__device__ __align__(16) int2   g_edge[NE];          // (src, w-as-int)
__device__ __align__(16) float  g_Wc1[DIN * NCAT];
__device__ __align__(16) __half g_Yr16[(size_t)NN * HID];  // rel half, fp16 (gathered)
__device__ __align__(16) float  g_Yroot[(size_t)NN * HID]; // root half, fp32
__device__ __align__(16) float  g_u[HID];   // W_rel3^T @ W_lin
__device__ __align__(16) float  g_v[HID];   // W_root3^T @ W_lin
__device__            float     g_c;        // W_lin . b3
__device__ __align__(16) float  g_s[NN];    // u . h1_i
__device__ __align__(16) float  g_r[NN];    // v . h1_i
__device__ __align__(16) float  g_z[NN];    // W_lin . h2_i

// ---------------- CSR build ----------------
__global__ void k_count(const int* __restrict__ ei) {
    int e = blockIdx.x * blockDim.x + threadIdx.x;
    if (e < NE) atomicAdd(&g_deg[ei[NE + e]], 1);
}

__global__ void k_scan() {
    __shared__ int wsum[32];
    const int tid = threadIdx.x;
    const int CH = (NN + 1023) / 1024;
    const int base = tid * CH;
    int s = 0;
    for (int i = 0; i < CH; i++) {
        int idx = base + i;
        if (idx < NN) s += g_deg[idx];
    }
    int lane = tid & 31, w = tid >> 5;
    int v = s;
    #pragma unroll
    for (int o = 1; o < 32; o <<= 1) {
        int n = __shfl_up_sync(0xffffffffu, v, o);
        if (lane >= o) v += n;
    }
    if (lane == 31) wsum[w] = v;
    __syncthreads();
    if (w == 0) {
        int x = wsum[lane];
        #pragma unroll
        for (int o = 1; o < 32; o <<= 1) {
            int n = __shfl_up_sync(0xffffffffu, x, o);
            if (lane >= o) x += n;
        }
        wsum[lane] = x;
    }
    __syncthreads();
    int excl = v - s + (w > 0 ? wsum[w - 1] : 0);
    int run = excl;
    for (int i = 0; i < CH; i++) {
        int idx = base + i;
        if (idx < NN) {
            g_off[idx] = run;
            g_cur[idx] = run;
            run += g_deg[idx];
            g_deg[idx] = 0;   // re-zero for next graph replay
        }
    }
    if (tid == 1023) g_off[NN] = run;
}

__global__ void k_scatter(const int* __restrict__ ei, const float* __restrict__ ea) {
    int e = blockIdx.x * blockDim.x + threadIdx.x;
    if (e < NE) {
        int d = ei[NE + e];
        int p = atomicAdd(&g_cur[d], 1);
        g_edge[p] = make_int2(ei[e], __float_as_int(ea[e]));
    }
}

// ---------------- weight prep ----------------
// layer-1 weights: transpose+concat into [K][256]
__global__ void k_prep_w(const float* __restrict__ Wr1, const float* __restrict__ Wro1) {
    int idx = blockIdx.x * blockDim.x + threadIdx.x;
    if (idx < DIN * NCAT) {
        int k = idx / NCAT, j = idx % NCAT;
        g_Wc1[idx] = (j < HID) ? Wr1[j * DIN + k] : Wro1[(j - HID) * DIN + k];
    }
}

// layer-2 + head fold: u = Wrel3^T Wlin, v = Wroot3^T Wlin, c = Wlin.b3
__global__ void k_prep_uv(const float* __restrict__ Wr3, const float* __restrict__ Wro3,
                          const float* __restrict__ Wl, const float* __restrict__ b3) {
    int k = threadIdx.x;  // 128
    float su = 0.f, sv = 0.f;
    #pragma unroll 4
    for (int j = 0; j < HID; j++) {
        float wl = Wl[j];
        su = fmaf(wl, Wr3[j * HID + k], su);
        sv = fmaf(wl, Wro3[j * HID + k], sv);
    }
    g_u[k] = su;
    g_v[k] = sv;
    if (k == 0) {
        float c = 0.f;
        for (int j = 0; j < HID; j++) c = fmaf(Wl[j], b3[j], c);
        g_c = c;
    }
}

// ---------------- fp32 SGEMM (layer 1 only): double-buffered, BK=16 ------------
// blockIdx.x==0 -> rel cols -> g_Yr16 (fp16); ==1 -> root cols -> g_Yroot (fp32)
__global__ __launch_bounds__(256) void k_sgemm(const float* __restrict__ A) {
    const int K = DIN;
    const float* __restrict__ B = g_Wc1;
    __shared__ float As[2][16][128];
    __shared__ float Bs[2][16][128];
    const int tid = threadIdx.x;
    const int m0 = blockIdx.y * 128;
    const int n0 = blockIdx.x * 128;
    const int ty = tid >> 4, tx = tid & 15;
    const int NI = K / 16;

    const int aR0 = tid >> 2, aC0 = (tid & 3) * 4;
    const int bK0 = tid >> 5, bN0 = (tid & 31) * 4;

    float4 pa[2], pb[2];
    auto ldA = [&](int k0) {
        #pragma unroll
        for (int i = 0; i < 2; i++) {
            int gr = m0 + aR0 + i * 64;
            pa[i] = (gr < NN) ? *(const float4*)(A + (size_t)gr * K + k0 + aC0)
                              : make_float4(0.f, 0.f, 0.f, 0.f);
        }
    };
    auto ldB = [&](int k0) {
        #pragma unroll
        for (int i = 0; i < 2; i++) {
            int kk = bK0 + i * 8;
            pb[i] = *(const float4*)(B + (size_t)(k0 + kk) * NCAT + n0 + bN0);
        }
    };
    auto stAB = [&](int buf) {
        #pragma unroll
        for (int i = 0; i < 2; i++) {
            int r = aR0 + i * 64;
            As[buf][aC0 + 0][r] = pa[i].x;
            As[buf][aC0 + 1][r] = pa[i].y;
            As[buf][aC0 + 2][r] = pa[i].z;
            As[buf][aC0 + 3][r] = pa[i].w;
            *(float4*)&Bs[buf][bK0 + i * 8][bN0] = pb[i];
        }
    };

    float acc[8][8];
    #pragma unroll
    for (int i = 0; i < 8; i++)
        #pragma unroll
        for (int j = 0; j < 8; j++) acc[i][j] = 0.f;

    ldA(0); ldB(0);
    stAB(0);
    __syncthreads();

    int buf = 0;
    for (int it = 0; it < NI; it++) {
        if (it + 1 < NI) { ldA((it + 1) * 16); ldB((it + 1) * 16); }
        #pragma unroll
        for (int k = 0; k < 16; k++) {
            const float4 a0 = *(const float4*)&As[buf][k][ty * 8];
            const float4 a1 = *(const float4*)&As[buf][k][ty * 8 + 4];
            const float4 b0 = *(const float4*)&Bs[buf][k][tx * 8];
            const float4 b1 = *(const float4*)&Bs[buf][k][tx * 8 + 4];
            const float ar[8] = {a0.x, a0.y, a0.z, a0.w, a1.x, a1.y, a1.z, a1.w};
            const float br[8] = {b0.x, b0.y, b0.z, b0.w, b1.x, b1.y, b1.z, b1.w};
            #pragma unroll
            for (int i = 0; i < 8; i++)
                #pragma unroll
                for (int j = 0; j < 8; j++)
                    acc[i][j] = fmaf(ar[i], br[j], acc[i][j]);
        }
        if (it + 1 < NI) stAB(buf ^ 1);
        __syncthreads();
        buf ^= 1;
    }

    const bool relPart = (blockIdx.x == 0);
    #pragma unroll
    for (int i = 0; i < 8; i++) {
        int r = m0 + ty * 8 + i;
        if (r >= NN) continue;
        if (relPart) {
            __half2 h0 = __floats2half2_rn(acc[i][0], acc[i][1]);
            __half2 h1 = __floats2half2_rn(acc[i][2], acc[i][3]);
            __half2 h2 = __floats2half2_rn(acc[i][4], acc[i][5]);
            __half2 h3 = __floats2half2_rn(acc[i][6], acc[i][7]);
            uint4 v;
            v.x = *(unsigned*)&h0; v.y = *(unsigned*)&h1;
            v.z = *(unsigned*)&h2; v.w = *(unsigned*)&h3;
            *(uint4*)(g_Yr16 + (size_t)r * HID + tx * 8) = v;
        } else {
            float* d0 = g_Yroot + (size_t)r * HID + tx * 8;
            *(float4*)(d0)     = make_float4(acc[i][0], acc[i][1], acc[i][2], acc[i][3]);
            *(float4*)(d0 + 4) = make_float4(acc[i][4], acc[i][5], acc[i][6], acc[i][7]);
        }
    }
}

// ---------------- layer-1 aggregation fused with u/v projection ----------------
// warp per node: h1 = relu(agg + root + b1) in registers -> s = u.h1, r = v.h1
__global__ void k_agg1(const float* __restrict__ bias) {
    int node = (blockIdx.x * blockDim.x + threadIdx.x) >> 5;
    if (node >= NN) return;
    int lane = threadIdx.x & 31;
    int beg = g_off[node], end = g_off[node + 1];
    float ax = 0.f, ay = 0.f, az = 0.f, aw = 0.f;
    float bx = 0.f, by = 0.f, bz = 0.f, bw = 0.f;
    int e = beg;
    for (; e + 1 < end; e += 2) {
        int2 e0 = g_edge[e];
        int2 e1 = g_edge[e + 1];
        uint2 v0 = *(const uint2*)(g_Yr16 + (size_t)e0.x * HID + 4 * lane);
        uint2 v1 = *(const uint2*)(g_Yr16 + (size_t)e1.x * HID + 4 * lane);
        float w0 = __int_as_float(e0.y);
        float w1 = __int_as_float(e1.y);
        float2 p00 = __half22float2(*(__half2*)&v0.x);
        float2 p01 = __half22float2(*(__half2*)&v0.y);
        float2 p10 = __half22float2(*(__half2*)&v1.x);
        float2 p11 = __half22float2(*(__half2*)&v1.y);
        ax = fmaf(p00.x, w0, ax); ay = fmaf(p00.y, w0, ay);
        az = fmaf(p01.x, w0, az); aw = fmaf(p01.y, w0, aw);
        bx = fmaf(p10.x, w1, bx); by = fmaf(p10.y, w1, by);
        bz = fmaf(p11.x, w1, bz); bw = fmaf(p11.y, w1, bw);
    }
    if (e < end) {
        int2 e0 = g_edge[e];
        uint2 v0 = *(const uint2*)(g_Yr16 + (size_t)e0.x * HID + 4 * lane);
        float w0 = __int_as_float(e0.y);
        float2 p00 = __half22float2(*(__half2*)&v0.x);
        float2 p01 = __half22float2(*(__half2*)&v0.y);
        ax = fmaf(p00.x, w0, ax); ay = fmaf(p00.y, w0, ay);
        az = fmaf(p01.x, w0, az); aw = fmaf(p01.y, w0, aw);
    }
    ax += bx; ay += by; az += bz; aw += bw;
    float4 rt = *(const float4*)(g_Yroot + (size_t)node * HID + 4 * lane);
    float4 bb = *(const float4*)(bias + 4 * lane);
    // h1 (post-relu) in registers
    float h0 = fmaxf(ax + rt.x + bb.x, 0.f);
    float h1 = fmaxf(ay + rt.y + bb.y, 0.f);
    float h2 = fmaxf(az + rt.z + bb.z, 0.f);
    float h3 = fmaxf(aw + rt.w + bb.w, 0.f);
    // project onto u and v
    float4 u4 = *(const float4*)(g_u + 4 * lane);
    float4 v4 = *(const float4*)(g_v + 4 * lane);
    float ps = h0 * u4.x + h1 * u4.y + h2 * u4.z + h3 * u4.w;
    float pr = h0 * v4.x + h1 * v4.y + h2 * v4.z + h3 * v4.w;
    #pragma unroll
    for (int o = 16; o > 0; o >>= 1) {
        ps += __shfl_down_sync(0xffffffffu, ps, o);
        pr += __shfl_down_sync(0xffffffffu, pr, o);
    }
    if (lane == 0) {
        g_s[node] = ps;
        g_r[node] = pr;
    }
}

// ---------------- layer-2 scalar aggregation: z = sum w*s[src] + r + c ---------
__global__ void k_agg2() {
    int node = blockIdx.x * blockDim.x + threadIdx.x;
    if (node >= NN) return;
    int beg = g_off[node], end = g_off[node + 1];
    float t = 0.f;
    for (int e = beg; e < end; e++) {
        int2 ed = g_edge[e];
        t = fmaf(__int_as_float(ed.y), g_s[ed.x], t);
    }
    g_z[node] = t + g_r[node] + g_c;
}

// ---------------- pooling + head: out = relu(mean(z) + bl) --------------------
__global__ void k_pool(const int* __restrict__ batch, const float* __restrict__ bl,
                       float* __restrict__ out) {
    int g = blockIdx.x;
    int c = threadIdx.x;  // 128
    int lo = 0, hi = NN;
    while (lo < hi) {
        int m = (lo + hi) >> 1;
        if (batch[m] < g) lo = m + 1; else hi = m;
    }
    int l = lo, h = NN;
    while (l < h) {
        int m = (l + h) >> 1;
        if (batch[m] < g + 1) l = m + 1; else h = m;
    }
    int cnt = l - lo;
    float s = 0.f;
    for (int i = lo + c; i < l; i += 128) s += g_z[i];
    __shared__ float red[128];
    red[c] = s;
    __syncthreads();
    for (int st = 64; st > 0; st >>= 1) {
        if (c < st) red[c] += red[c + st];
        __syncthreads();
    }
    if (c == 0) {
        float p = red[0] / fmaxf((float)cnt, 1.f);
        out[g] = fmaxf(p + bl[0], 0.f);
    }
}

// ---------------- launch (serial; fork experiment reverted) -------------------
extern "C" void kernel_launch(void* const* d_in, const int* in_sizes, int n_in,
                              void* d_out, int out_size) {
    const float* x     = (const float*)d_in[0];
    const int*   ei    = (const int*)d_in[1];
    const int*   batch = (const int*)d_in[2];
    const float* ea    = (const float*)d_in[3];
    const float* Wr1   = (const float*)d_in[4];
    const float* b1    = (const float*)d_in[5];
    const float* Wro1  = (const float*)d_in[6];
    const float* Wr3   = (const float*)d_in[7];
    const float* b3    = (const float*)d_in[8];
    const float* Wro3  = (const float*)d_in[9];
    const float* Wl    = (const float*)d_in[10];
    const float* bl    = (const float*)d_in[11];
    float* out = (float*)d_out;

    k_count<<<(NE + 255) / 256, 256>>>(ei);
    k_scan<<<1, 1024>>>();
    k_scatter<<<(NE + 255) / 256, 256>>>(ei, ea);
    k_prep_w<<<(DIN * NCAT + 255) / 256, 256>>>(Wr1, Wro1);
    k_prep_uv<<<1, 128>>>(Wr3, Wro3, Wl, b3);

    dim3 ggrid(2, (NN + 127) / 128);
    k_sgemm<<<ggrid, 256>>>(x);
    k_agg1<<<(NN * 32 + 255) / 256, 256>>>(b1);
    k_agg2<<<(NN + 255) / 256, 256>>>();
    k_pool<<<NG, 128>>>(batch, bl, out);
}